// round 7
// baseline (speedup 1.0000x reference)
#include <cuda_runtime.h>
#include <math.h>

#define BB 4
#define NX 4096
#define NY 4096
#define FF 16

typedef unsigned long long u64;

// Packed f32x2 helpers (Blackwell sm_103a; ptxas never auto-generates these)
__device__ __forceinline__ u64 pk2(float lo, float hi) {
    u64 r; asm("mov.b64 %0, {%1, %2};" : "=l"(r) : "f"(lo), "f"(hi)); return r;
}
__device__ __forceinline__ void upk2(float& lo, float& hi, u64 v) {
    asm("mov.b64 {%0, %1}, %2;" : "=f"(lo), "=f"(hi) : "l"(v));
}
__device__ __forceinline__ u64 fma2_(u64 a, u64 b, u64 c) {
    u64 d; asm("fma.rn.f32x2 %0, %1, %2, %3;" : "=l"(d) : "l"(a), "l"(b), "l"(c)); return d;
}
__device__ __forceinline__ u64 add2_(u64 a, u64 b) {
    u64 d; asm("add.rn.f32x2 %0, %1, %2;" : "=l"(d) : "l"(a), "l"(b)); return d;
}
__device__ __forceinline__ u64 mul2_(u64 a, u64 b) {
    u64 d; asm("mul.rn.f32x2 %0, %1, %2;" : "=l"(d) : "l"(a), "l"(b)); return d;
}
__device__ __forceinline__ float rcpf(float a) {
    float r; asm("rcp.approx.ftz.f32 %0, %1;" : "=f"(r) : "f"(a)); return r;
}

// ---------------------------------------------------------------------------
// Single fused kernel. 256 threads -> tile of TI=16 rows x 1024 cols.
// Prologue computes, per block, the per-row (cx, ssx) and per-thread
// per-column (cy, ssy) values inline — no separate precompute launch, no
// global scratch. Inner math in packed f32x2; plain float4 stores (the
// streaming .cs variant saturates L1tex on sm_103a — measured 2.7x wavefront
// inflation in R6).
// ---------------------------------------------------------------------------
#define TI 16
#define TJ_THREAD 4
#define THREADS 256
#define TJ (THREADS * TJ_THREAD)  // 1024

__global__ __launch_bounds__(THREADS)
void cauchy_fused_kernel(const float* __restrict__ x,
                         const float* __restrict__ y,
                         const float* __restrict__ sample_x,
                         const float* __restrict__ sample_y,
                         const float* __restrict__ scale,
                         float* __restrict__ out) {
    const int b = blockIdx.z;
    const int i0 = blockIdx.y * TI;
    const int j0 = blockIdx.x * TJ + threadIdx.x * TJ_THREAD;

    __shared__ float s_scale[FF];
    __shared__ float2 sA0[TI], sA1[TI], sA2[TI], sC[TI], sS[TI];

    if (threadIdx.x < FF) {
        s_scale[threadIdx.x] = fminf(fmaxf(scale[threadIdx.x], 1e-6f), 1e6f);
    }
    __syncthreads();

    // ---- y-side prologue: each thread computes cy/ssy for its 4 columns ----
    const int gj = b * NY + j0;
    const float4* yp = reinterpret_cast<const float4*>(y + (size_t)gj * 3);
    float4 ya = yp[0];
    float4 yb = yp[1];
    float4 yc = yp[2];
    // Per-coordinate packed pairs: pair 0 = cols {0,1}, pair 1 = cols {2,3}
    u64 y0p[2] = { pk2(ya.x, ya.w), pk2(yb.z, yc.y) };
    u64 y1p[2] = { pk2(ya.y, yb.x), pk2(yb.w, yc.z) };
    u64 y2p[2] = { pk2(ya.z, yb.y), pk2(yc.x, yc.w) };

    float cyv[4], syv[4];
    {
        // cy = ||y||^2 per column
        float yy0[4] = {ya.x, ya.w, yb.z, yc.y};
        float yy1[4] = {ya.y, yb.x, yb.w, yc.z};
        float yy2[4] = {ya.z, yb.y, yc.x, yc.w};
#pragma unroll
        for (int u = 0; u < 4; u++) {
            cyv[u] = yy0[u] * yy0[u] + yy1[u] * yy1[u] + yy2[u] * yy2[u];
            const float4* sp = reinterpret_cast<const float4*>(
                sample_y + (size_t)(gj + u) * FF);
            float dot = 0.0f;
#pragma unroll
            for (int q = 0; q < FF / 4; q++) {
                float4 v = sp[q];
                dot = fmaf(v.x, s_scale[q * 4 + 0], dot);
                dot = fmaf(v.y, s_scale[q * 4 + 1], dot);
                dot = fmaf(v.z, s_scale[q * 4 + 2], dot);
                dot = fmaf(v.w, s_scale[q * 4 + 3], dot);
            }
            syv[u] = sqrtf(fminf(fmaxf(dot, 1e-10f), 1e6f));
        }
    }
    u64 cyp[2] = { pk2(cyv[0], cyv[1]), pk2(cyv[2], cyv[3]) };
    u64 syp[2] = { pk2(syv[0], syv[1]), pk2(syv[2], syv[3]) };

    // ---- x-side prologue: 16 threads compute row data into smem ----
    if (threadIdx.x < TI) {
        int gi = b * NX + i0 + threadIdx.x;
        float p0 = x[gi * 3 + 0];
        float p1 = x[gi * 3 + 1];
        float p2 = x[gi * 3 + 2];
        float c = p0 * p0 + p1 * p1 + p2 * p2;
        const float4* sp = reinterpret_cast<const float4*>(
            sample_x + (size_t)gi * FF);
        float dot = 0.0f;
#pragma unroll
        for (int q = 0; q < FF / 4; q++) {
            float4 v = sp[q];
            dot = fmaf(v.x, s_scale[q * 4 + 0], dot);
            dot = fmaf(v.y, s_scale[q * 4 + 1], dot);
            dot = fmaf(v.z, s_scale[q * 4 + 2], dot);
            dot = fmaf(v.w, s_scale[q * 4 + 3], dot);
        }
        float ss = sqrtf(fminf(fmaxf(dot, 1e-10f), 1e6f));
        float a0 = -2.0f * p0;
        float a1 = -2.0f * p1;
        float a2 = -2.0f * p2;
        sA0[threadIdx.x] = make_float2(a0, a0);
        sA1[threadIdx.x] = make_float2(a1, a1);
        sA2[threadIdx.x] = make_float2(a2, a2);
        sC[threadIdx.x]  = make_float2(c, c);
        sS[threadIdx.x]  = make_float2(ss, ss);
    }
    __syncthreads();

    // ---- Main loop ----
    float* orow = out + ((size_t)(b * NX + i0)) * NY + j0;

#pragma unroll 4
    for (int ti = 0; ti < TI; ti++) {
        u64 a0p = *reinterpret_cast<const u64*>(&sA0[ti]);
        u64 a1p = *reinterpret_cast<const u64*>(&sA1[ti]);
        u64 a2p = *reinterpret_cast<const u64*>(&sA2[ti]);
        u64 ccp = *reinterpret_cast<const u64*>(&sC[ti]);
        u64 sap = *reinterpret_cast<const u64*>(&sS[ti]);

        // d = (cx + cy) - 2*x.y   (packed, 2 outputs per op)
        u64 d0 = fma2_(a2p, y2p[0], add2_(ccp, cyp[0]));
        d0 = fma2_(a1p, y1p[0], d0);
        d0 = fma2_(a0p, y0p[0], d0);
        u64 d1 = fma2_(a2p, y2p[1], add2_(ccp, cyp[1]));
        d1 = fma2_(a1p, y1p[1], d1);
        d1 = fma2_(a0p, y0p[1], d1);

        // sxy = sqrt(sx)*sqrt(sy)  (outer clamps provably never bind here)
        u64 sxy0 = mul2_(sap, syp[0]);
        u64 sxy1 = mul2_(sap, syp[1]);

        // r = sxy / (sxy + d)
        u64 den0 = add2_(d0, sxy0);
        u64 den1 = add2_(d1, sxy1);
        float e0, e1, e2, e3;
        upk2(e0, e1, den0);
        upk2(e2, e3, den1);
        u64 rp0 = pk2(rcpf(e0), rcpf(e1));
        u64 rp1 = pk2(rcpf(e2), rcpf(e3));
        u64 r0 = mul2_(sxy0, rp0);
        u64 r1 = mul2_(sxy1, rp1);

        float4 res;
        *reinterpret_cast<u64*>(&res.x) = r0;
        *reinterpret_cast<u64*>(&res.z) = r1;
        *reinterpret_cast<float4*>(orow + (size_t)ti * NY) = res;
    }
}

// ---------------------------------------------------------------------------
extern "C" void kernel_launch(void* const* d_in, const int* in_sizes, int n_in,
                              void* d_out, int out_size) {
    const float* x        = (const float*)d_in[0];  // (B,NX,3)
    const float* y        = (const float*)d_in[1];  // (B,NY,3)
    const float* sample_x = (const float*)d_in[2];  // (B,NX,F)
    const float* sample_y = (const float*)d_in[3];  // (B,NY,F)
    const float* scale    = (const float*)d_in[4];  // (F,)
    float* out = (float*)d_out;                     // (B,NX,NY)

    dim3 grid(NY / TJ, NX / TI, BB);
    cauchy_fused_kernel<<<grid, THREADS>>>(x, y, sample_x, sample_y, scale, out);
}

// round 8
// speedup vs baseline: 2.0879x; 2.0879x over previous
#include <cuda_runtime.h>
#include <math.h>

#define BB 4
#define NX 4096
#define NY 4096
#define FF 16

typedef unsigned long long u64;

// Packed f32x2 helpers (Blackwell sm_103a; ptxas never auto-generates these)
__device__ __forceinline__ u64 pk2(float lo, float hi) {
    u64 r; asm("mov.b64 %0, {%1, %2};" : "=l"(r) : "f"(lo), "f"(hi)); return r;
}
__device__ __forceinline__ void upk2(float& lo, float& hi, u64 v) {
    asm("mov.b64 {%0, %1}, %2;" : "=f"(lo), "=f"(hi) : "l"(v));
}
__device__ __forceinline__ u64 fma2_(u64 a, u64 b, u64 c) {
    u64 d; asm("fma.rn.f32x2 %0, %1, %2, %3;" : "=l"(d) : "l"(a), "l"(b), "l"(c)); return d;
}
__device__ __forceinline__ u64 add2_(u64 a, u64 b) {
    u64 d; asm("add.rn.f32x2 %0, %1, %2;" : "=l"(d) : "l"(a), "l"(b)); return d;
}
__device__ __forceinline__ u64 mul2_(u64 a, u64 b) {
    u64 d; asm("mul.rn.f32x2 %0, %1, %2;" : "=l"(d) : "l"(a), "l"(b)); return d;
}
__device__ __forceinline__ float rcpf(float a) {
    float r; asm("rcp.approx.ftz.f32 %0, %1;" : "=f"(r) : "f"(a)); return r;
}

// y-side scratch: each column's cy/ssy computed ONCE (not once per block)
__device__ float g_cy[BB * NY];
__device__ float g_ssy[BB * NY];

// ---------------------------------------------------------------------------
// Precompute (y-side only): per-point sq-norm + sqrt of clipped scale-dot.
// 16384 points. Signals programmatic launch completion immediately so the
// dependent main kernel overlaps its launch ramp + independent prologue.
// ---------------------------------------------------------------------------
__global__ void precompute_y_kernel(const float* __restrict__ ypts,
                                    const float* __restrict__ ysamp,
                                    const float* __restrict__ scale,
                                    float* __restrict__ cy_out,
                                    float* __restrict__ ssy_out,
                                    int npts) {
    cudaTriggerProgrammaticLaunchCompletion();

    __shared__ float s[FF];
    if (threadIdx.x < FF) {
        s[threadIdx.x] = fminf(fmaxf(scale[threadIdx.x], 1e-6f), 1e6f);
    }
    __syncthreads();

    int i = blockIdx.x * blockDim.x + threadIdx.x;
    if (i >= npts) return;

    float p0 = ypts[i * 3 + 0];
    float p1 = ypts[i * 3 + 1];
    float p2 = ypts[i * 3 + 2];
    float c = p0 * p0 + p1 * p1 + p2 * p2;

    const float4* sp = reinterpret_cast<const float4*>(ysamp + (size_t)i * FF);
    float dot = 0.0f;
#pragma unroll
    for (int q = 0; q < FF / 4; q++) {
        float4 v = sp[q];
        dot = fmaf(v.x, s[q * 4 + 0], dot);
        dot = fmaf(v.y, s[q * 4 + 1], dot);
        dot = fmaf(v.z, s[q * 4 + 2], dot);
        dot = fmaf(v.w, s[q * 4 + 3], dot);
    }
    float sx = fminf(fmaxf(dot, 1e-10f), 1e6f);

    cy_out[i] = c;
    ssy_out[i] = sqrtf(sx);
}

// ---------------------------------------------------------------------------
// Main pairwise kernel (R4-proven shape): 256 threads -> 16 rows x 1024 cols.
// x-side (only 16 rows/block) computed inline in the independent prologue;
// y-side read from precomputed scratch after the PDL grid sync.
// ---------------------------------------------------------------------------
#define TI 16
#define TJ_THREAD 4
#define THREADS 256
#define TJ (THREADS * TJ_THREAD)  // 1024

__global__ __launch_bounds__(THREADS)
void cauchy_main_kernel(const float* __restrict__ x,
                        const float* __restrict__ y,
                        const float* __restrict__ sample_x,
                        const float* __restrict__ scale,
                        float* __restrict__ out) {
    const int b = blockIdx.z;
    const int i0 = blockIdx.y * TI;
    const int j0 = blockIdx.x * TJ + threadIdx.x * TJ_THREAD;

    __shared__ float s_scale[FF];
    __shared__ float2 sA0[TI], sA1[TI], sA2[TI], sC[TI], sS[TI];

    // ---- Independent prologue (no dependence on precompute output) ----
    if (threadIdx.x < FF) {
        s_scale[threadIdx.x] = fminf(fmaxf(scale[threadIdx.x], 1e-6f), 1e6f);
    }
    __syncthreads();

    // y coords: 12 contiguous floats -> 3 float4 loads (coalesced)
    const int gj = b * NY + j0;
    const float4* yp = reinterpret_cast<const float4*>(y + (size_t)gj * 3);
    float4 ya = yp[0];
    float4 yb = yp[1];
    float4 yc = yp[2];
    u64 y0p[2] = { pk2(ya.x, ya.w), pk2(yb.z, yc.y) };
    u64 y1p[2] = { pk2(ya.y, yb.x), pk2(yb.w, yc.z) };
    u64 y2p[2] = { pk2(ya.z, yb.y), pk2(yc.x, yc.w) };

    // x-side inline: 16 threads, 4 small loads each — negligible L1 traffic
    if (threadIdx.x < TI) {
        int gi = b * NX + i0 + threadIdx.x;
        float p0 = x[gi * 3 + 0];
        float p1 = x[gi * 3 + 1];
        float p2 = x[gi * 3 + 2];
        float c = p0 * p0 + p1 * p1 + p2 * p2;
        const float4* sp = reinterpret_cast<const float4*>(
            sample_x + (size_t)gi * FF);
        float dot = 0.0f;
#pragma unroll
        for (int q = 0; q < FF / 4; q++) {
            float4 v = sp[q];
            dot = fmaf(v.x, s_scale[q * 4 + 0], dot);
            dot = fmaf(v.y, s_scale[q * 4 + 1], dot);
            dot = fmaf(v.z, s_scale[q * 4 + 2], dot);
            dot = fmaf(v.w, s_scale[q * 4 + 3], dot);
        }
        float ss = sqrtf(fminf(fmaxf(dot, 1e-10f), 1e6f));
        float a0 = -2.0f * p0;
        float a1 = -2.0f * p1;
        float a2 = -2.0f * p2;
        sA0[threadIdx.x] = make_float2(a0, a0);
        sA1[threadIdx.x] = make_float2(a1, a1);
        sA2[threadIdx.x] = make_float2(a2, a2);
        sC[threadIdx.x]  = make_float2(c, c);
        sS[threadIdx.x]  = make_float2(ss, ss);
    }

    // ---- Wait for precompute grid, then consume y-side scratch ----
    cudaGridDependencySynchronize();

    float4 cy4 = *reinterpret_cast<const float4*>(g_cy + gj);
    float4 sy4 = *reinterpret_cast<const float4*>(g_ssy + gj);
    u64 cyp[2] = { pk2(cy4.x, cy4.y), pk2(cy4.z, cy4.w) };
    u64 syp[2] = { pk2(sy4.x, sy4.y), pk2(sy4.z, sy4.w) };

    __syncthreads();

    float* orow = out + ((size_t)(b * NX + i0)) * NY + j0;

#pragma unroll 4
    for (int ti = 0; ti < TI; ti++) {
        u64 a0p = *reinterpret_cast<const u64*>(&sA0[ti]);
        u64 a1p = *reinterpret_cast<const u64*>(&sA1[ti]);
        u64 a2p = *reinterpret_cast<const u64*>(&sA2[ti]);
        u64 ccp = *reinterpret_cast<const u64*>(&sC[ti]);
        u64 sap = *reinterpret_cast<const u64*>(&sS[ti]);

        // d = (cx + cy) - 2*x.y   (packed, 2 outputs per op)
        u64 d0 = fma2_(a2p, y2p[0], add2_(ccp, cyp[0]));
        d0 = fma2_(a1p, y1p[0], d0);
        d0 = fma2_(a0p, y0p[0], d0);
        u64 d1 = fma2_(a2p, y2p[1], add2_(ccp, cyp[1]));
        d1 = fma2_(a1p, y1p[1], d1);
        d1 = fma2_(a0p, y0p[1], d1);

        // sxy = sqrt(sx)*sqrt(sy)  (outer clamps provably never bind here)
        u64 sxy0 = mul2_(sap, syp[0]);
        u64 sxy1 = mul2_(sap, syp[1]);

        // r = sxy / (sxy + d)
        u64 den0 = add2_(d0, sxy0);
        u64 den1 = add2_(d1, sxy1);
        float e0, e1, e2, e3;
        upk2(e0, e1, den0);
        upk2(e2, e3, den1);
        u64 rp0 = pk2(rcpf(e0), rcpf(e1));
        u64 rp1 = pk2(rcpf(e2), rcpf(e3));
        u64 r0 = mul2_(sxy0, rp0);
        u64 r1 = mul2_(sxy1, rp1);

        float4 res;
        *reinterpret_cast<u64*>(&res.x) = r0;
        *reinterpret_cast<u64*>(&res.z) = r1;
        *reinterpret_cast<float4*>(orow + (size_t)ti * NY) = res;
    }
}

// ---------------------------------------------------------------------------
extern "C" void kernel_launch(void* const* d_in, const int* in_sizes, int n_in,
                              void* d_out, int out_size) {
    const float* x        = (const float*)d_in[0];  // (B,NX,3)
    const float* y        = (const float*)d_in[1];  // (B,NY,3)
    const float* sample_x = (const float*)d_in[2];  // (B,NX,F)
    const float* sample_y = (const float*)d_in[3];  // (B,NY,F)
    const float* scale    = (const float*)d_in[4];  // (F,)
    float* out = (float*)d_out;                     // (B,NX,NY)

    float* cy;  cudaGetSymbolAddress((void**)&cy,  g_cy);
    float* ssy; cudaGetSymbolAddress((void**)&ssy, g_ssy);

    const int npts = BB * NY;
    precompute_y_kernel<<<(npts + 255) / 256, 256>>>(
        y, sample_y, scale, cy, ssy, npts);

    // Main kernel with Programmatic Dependent Launch: overlaps its launch ramp
    // and independent prologue with the precompute grid.
    cudaLaunchConfig_t cfg = {};
    cfg.gridDim = dim3(NY / TJ, NX / TI, BB);
    cfg.blockDim = dim3(THREADS, 1, 1);
    cfg.dynamicSmemBytes = 0;
    cfg.stream = 0;
    cudaLaunchAttribute attr[1];
    attr[0].id = cudaLaunchAttributeProgrammaticStreamSerialization;
    attr[0].val.programmaticStreamSerializationAllowed = 1;
    cfg.attrs = attr;
    cfg.numAttrs = 1;
    cudaLaunchKernelEx(&cfg, cauchy_main_kernel, x, y, sample_x, scale, out);
}